// round 3
// baseline (speedup 1.0000x reference)
#include <cuda_runtime.h>
#include <cuda_bf16.h>

#define THREADS 256
#define PER 32                 // elements per thread
#define COLS 8192
#define WBUF 96                // candidate buffer (window cap is 64)

// order-preserving float->uint key: ascending uint order == ascending float order
__device__ __forceinline__ unsigned f2k(float f) {
    unsigned u = __float_as_uint(f);
    return (u & 0x80000000u) ? ~u : (u | 0x80000000u);
}
__device__ __forceinline__ float k2f(unsigned kk) {
    unsigned u = (kk & 0x80000000u) ? (kk ^ 0x80000000u) : ~kk;
    return __uint_as_float(u);
}

__global__ void __launch_bounds__(THREADS) rsoftmax_kernel(
    const float* __restrict__ in,
    const float* __restrict__ rate_p,
    float* __restrict__ out)
{
    __shared__ int      s_part[8];
    __shared__ unsigned s_minp[8], s_maxp[8];
    __shared__ float    s_facc[8];
    __shared__ unsigned s_lo, s_hi, s_T;
    __shared__ int      s_clo, s_cle, s_done, s_m;
    __shared__ float    s_inv;
    __shared__ unsigned s_buf[WBUF];

    const int tid  = threadIdx.x;
    const int lane = tid & 31;
    const int wid  = tid >> 5;
    const int row  = blockIdx.x;
    const float* rp = in  + (size_t)row * COLS;
    float*       op = out + (size_t)row * COLS;

    // ---- rank from sparsity_rate (uniform) ----
    float r = rate_p[0];
    r = fminf(fmaxf(r, 0.0f), 1.0f);
    int idx = (int)(r * (float)COLS);        // trunc, matches astype(int32)
    if (idx > COLS - 1) idx = COLS - 1;      // jnp.take clip semantics
    const int k = (COLS - 1) - idx;          // k-th smallest (0-indexed)

    // ---- load row -> register keys, fused min/max ----
    unsigned key[PER];
    unsigned kmin = 0xFFFFFFFFu, kmax = 0u;
#pragma unroll
    for (int j = 0; j < PER / 4; j++) {
        float4 v = ((const float4*)rp)[j * THREADS + tid];
        unsigned k0 = f2k(v.x), k1 = f2k(v.y), k2 = f2k(v.z), k3 = f2k(v.w);
        key[4*j+0] = k0; key[4*j+1] = k1; key[4*j+2] = k2; key[4*j+3] = k3;
        kmin = min(kmin, min(min(k0, k1), min(k2, k3)));
        kmax = max(kmax, max(max(k0, k1), max(k2, k3)));
    }
#pragma unroll
    for (int o = 16; o; o >>= 1) {
        kmin = min(kmin, __shfl_down_sync(0xffffffffu, kmin, o));
        kmax = max(kmax, __shfl_down_sync(0xffffffffu, kmax, o));
    }
    if (lane == 0) { s_minp[wid] = kmin; s_maxp[wid] = kmax; }
    if (tid == 0)  { s_m = 0; s_done = 0; }
    __syncthreads();
    if (tid == 0) {
        unsigned lo = s_minp[0], hi = s_maxp[0];
#pragma unroll
        for (int w = 1; w < 8; w++) { lo = min(lo, s_minp[w]); hi = max(hi, s_maxp[w]); }
        s_lo = lo; s_hi = hi; s_clo = 0; s_cle = COLS;
        if (lo >= hi) { s_done = 1; s_T = lo; }
    }
    __syncthreads();

    // ---- selection: interpolated counting bisection over register keys ----
    // invariant: cnt(< lo) = clo <= k < cnt(<= hi) = cle ; answer in [lo, hi]
    for (int iter = 0; iter < 72; iter++) {
        if (s_done) break;                       // uniform (post-barrier)
        unsigned lo = s_lo, hi = s_hi;
        int clo = s_clo, cle = s_cle;
        int cw = cle - clo;
        if (cw <= 64) break;                     // small window -> compaction

        unsigned p;
        if (iter & 1) {                          // guaranteed-progress midpoint
            p = lo + ((hi - lo + 1u) >> 1);
        } else {                                 // value-space interpolation
            float flo = k2f(lo), fhi = k2f(hi);
            float frac = ((float)(k - clo) + 0.5f) / (float)cw;
            float pf = flo + (fhi - flo) * frac;
            p = f2k(pf);
            if (p <= lo) p = lo + 1u;
            if (p > hi)  p = hi;
        }

        int c = 0;
#pragma unroll
        for (int j = 0; j < PER; j++) c += (key[j] < p);
#pragma unroll
        for (int o = 16; o; o >>= 1) c += __shfl_down_sync(0xffffffffu, c, o);
        if (lane == 0) s_part[wid] = c;
        __syncthreads();
        if (tid == 0) {
            int ct = 0;
#pragma unroll
            for (int w = 0; w < 8; w++) ct += s_part[w];
            if (ct > k) { s_hi = p - 1u; s_cle = ct; }   // answer < p
            else        { s_lo = p;      s_clo = ct; }   // answer >= p
            if (s_lo >= s_hi) { s_done = 1; s_T = s_lo; }
        }
        __syncthreads();
    }

    // ---- compact small window and brute-force exact rank ----
    if (!s_done) {                               // uniform
        unsigned lo = s_lo, hi = s_hi;
#pragma unroll
        for (int j = 0; j < PER; j++) {
            unsigned kk = key[j];
            if (kk >= lo && kk <= hi) {
                int pos = atomicAdd(&s_m, 1);
                if (pos < WBUF) s_buf[pos] = kk;
            }
        }
        __syncthreads();
        int m  = s_m; if (m > WBUF) m = WBUF;
        int rr = k - s_clo;                      // rank within window
        if (tid < m) {
            unsigned x = s_buf[tid];
            int less = 0, leq = 0;
            for (int j2 = 0; j2 < m; j2++) {
                unsigned v = s_buf[j2];
                less += (v <  x);
                leq  += (v <= x);
            }
            if (less <= rr && rr < leq) s_T = x;  // duplicates write same value
        }
        __syncthreads();
    }
    const float thresh = k2f(s_T);

    // ---- epilogue: we = relu(x - thresh) * exp(x); overwrite key regs ----
    float acc = 0.0f;
#pragma unroll
    for (int j = 0; j < PER; j++) {
        float x  = k2f(key[j]);
        float w  = fmaxf(x - thresh, 0.0f);
        float we = w * __expf(x);
        key[j] = __float_as_uint(we);
        acc += we;
    }
#pragma unroll
    for (int o = 16; o; o >>= 1) acc += __shfl_down_sync(0xffffffffu, acc, o);
    if (lane == 0) s_facc[wid] = acc;
    __syncthreads();
    if (tid == 0) {
        float s = 0.0f;
#pragma unroll
        for (int w = 0; w < 8; w++) s += s_facc[w];
        s_inv = 1.0f / s;
    }
    __syncthreads();
    const float inv = s_inv;

#pragma unroll
    for (int j = 0; j < PER / 4; j++) {
        float4 v;
        v.x = __uint_as_float(key[4*j+0]) * inv;
        v.y = __uint_as_float(key[4*j+1]) * inv;
        v.z = __uint_as_float(key[4*j+2]) * inv;
        v.w = __uint_as_float(key[4*j+3]) * inv;
        ((float4*)op)[j * THREADS + tid] = v;
    }
}

extern "C" void kernel_launch(void* const* d_in, const int* in_sizes, int n_in,
                              void* d_out, int out_size) {
    const float* in     = (const float*)d_in[0];
    const float* rate_p = (const float*)d_in[1];
    float*       out    = (float*)d_out;
    const int rows = in_sizes[0] / COLS;   // 8192
    rsoftmax_kernel<<<rows, THREADS>>>(in, rate_p, out);
}

// round 4
// speedup vs baseline: 1.1649x; 1.1649x over previous
#include <cuda_runtime.h>

#define THREADS 256
#define PER 32                 // elements per thread
#define COLS 8192
#define WBUF 2048              // analytic-bracket candidate buffer
#define FBUF 96                // final small window buffer

// order-preserving float<->uint key (used only on scalars / fallback pivots)
__device__ __forceinline__ unsigned f2k(float f) {
    unsigned u = __float_as_uint(f);
    return (u & 0x80000000u) ? ~u : (u | 0x80000000u);
}
__device__ __forceinline__ float k2f(unsigned kk) {
    unsigned u = (kk & 0x80000000u) ? (kk ^ 0x80000000u) : ~kk;
    return __uint_as_float(u);
}

__global__ void __launch_bounds__(THREADS) rsoftmax_kernel(
    const float* __restrict__ in,
    const float* __restrict__ rate_p,
    float* __restrict__ out)
{
    __shared__ int      s_part[8];
    __shared__ float    s_facc[8];
    __shared__ unsigned s_lo, s_hi;
    __shared__ int      s_clo, s_cle, s_done, s_m2;
    __shared__ float    s_T, s_inv;
    __shared__ float    s_buf[WBUF + 1];   // +1 dummy slot for branch-free compaction
    __shared__ float    s_fb[FBUF];

    const int tid  = threadIdx.x;
    const int lane = tid & 31;
    const int wid  = tid >> 5;
    const float* rp = in  + (size_t)blockIdx.x * COLS;
    float*       op = out + (size_t)blockIdx.x * COLS;

    // ---- rank from sparsity_rate (uniform) ----
    float r = fminf(fmaxf(rate_p[0], 0.0f), 1.0f);
    int idx = (int)(r * (float)COLS);        // trunc, matches astype(int32)
    if (idx > COLS - 1) idx = COLS - 1;      // jnp.take clamp semantics
    const int k = (COLS - 1) - idx;          // k-th smallest (0-indexed)

    // ---- analytic Gaussian bracket (prior only; exact fallback below) ----
    float q = ((float)k + 0.5f) / (float)COLS;
    q = fminf(fmaxf(q, 4.0e-5f), 1.0f - 4.0e-5f);
    float c   = normcdfinvf(q);
    float pdf = 0.3989423f * __expf(-0.5f * c * c);
    float hw  = 6.0f * sqrtf(q * (1.0f - q) * (1.0f / (float)COLS)) / pdf + 0.02f;
    const float A = c - hw, B = c + hw;

    // ---- load row into registers (front-batched float4, max MLP) ----
    float x[PER];
#pragma unroll
    for (int j = 0; j < PER / 4; j++) {
        float4 v = ((const float4*)rp)[j * THREADS + tid];
        x[4*j+0] = v.x; x[4*j+1] = v.y; x[4*j+2] = v.z; x[4*j+3] = v.w;
    }

    if (tid == 0) { s_done = 0; s_m2 = 0; }

    // ---- pass 1: per-thread counts vs bracket ----
    int cl = 0, ch = 0;
#pragma unroll
    for (int j = 0; j < PER; j++) {
        cl += (x[j] <  A);
        ch += (x[j] <= B);
    }
    // block scan of packed (cl | ch<<16): gives totals + per-thread write base
    unsigned pack = (unsigned)cl | ((unsigned)ch << 16);
    unsigned incl = pack;
#pragma unroll
    for (int o = 1; o < 32; o <<= 1) {
        unsigned t = __shfl_up_sync(0xffffffffu, incl, o);
        if (lane >= o) incl += t;
    }
    if (lane == 31) s_part[wid] = (int)incl;
    __syncthreads();
    unsigned wpre = 0, tot = 0;
#pragma unroll
    for (int w = 0; w < 8; w++) {
        unsigned v = (unsigned)s_part[w];
        tot += v;
        if (w < wid) wpre += v;
    }
    const int Clo = (int)(tot & 0xffffu);
    const int Che = (int)(tot >> 16);
    const int M   = Che - Clo;                     // candidates in [A,B]
    unsigned epre = wpre + incl - pack;            // exclusive prefix (packed)
    int base = (int)(epre >> 16) - (int)(epre & 0xffffu);

    const bool ok = (Clo <= k) && (k < Che) && (M <= WBUF);   // block-uniform
    float thresh;

    if (ok) {
        const int nslots = (M + THREADS - 1) / THREADS;
        // ---- pass 2: branch-free compaction to smem ----
#pragma unroll
        for (int j = 0; j < PER; j++) {
            int inr = (x[j] >= A) & (x[j] <= B);
            int widx = inr ? base : WBUF;          // non-candidates -> dummy slot
            s_buf[widx] = x[j];
            base += inr;
        }
        for (int id = M + tid; id < nslots * THREADS; id += THREADS)
            s_buf[id] = __int_as_float(0x7f800000);   // +inf pad

        // ---- stage 2: counting bisection over smem candidates ----
        const int rr = k - Clo;                    // rank within candidates
        if (tid == 0) {
            s_lo = f2k(A); s_hi = f2k(B); s_clo = 0; s_cle = M;
            if (s_lo >= s_hi) { s_done = 1; s_T = A; }
        }
        __syncthreads();

        for (int iter = 0; iter < 72; iter++) {
            if (s_done) break;                     // uniform (post-barrier)
            unsigned lo = s_lo, hi = s_hi;
            int clo = s_clo, cle = s_cle, cw = cle - clo;
            if (cw <= 64) break;
            unsigned p;
            if (iter & 1) {                        // guaranteed-progress midpoint
                p = lo + ((hi - lo + 1u) >> 1);
            } else {                               // value-space interpolation
                float flo = k2f(lo), fhi = k2f(hi);
                float frac = ((float)(rr - clo) + 0.5f) / (float)cw;
                p = f2k(flo + (fhi - flo) * frac);
                if (p <= lo) p = lo + 1u;
                if (p > hi)  p = hi;
            }
            float pf = k2f(p);
            int cnt = 0;
            for (int i = 0; i < nslots; i++)
                cnt += (s_buf[i * THREADS + tid] < pf);
#pragma unroll
            for (int o = 16; o; o >>= 1) cnt += __shfl_down_sync(0xffffffffu, cnt, o);
            if (lane == 0) s_part[wid] = cnt;
            __syncthreads();
            if (tid == 0) {
                int ct = 0;
#pragma unroll
                for (int w = 0; w < 8; w++) ct += s_part[w];
                if (ct > rr) { s_hi = p - 1u; s_cle = ct; }
                else         { s_lo = p;      s_clo = ct; }
                if (s_lo >= s_hi) { s_done = 1; s_T = k2f(s_lo); }
            }
            __syncthreads();
        }

        if (!s_done) {                             // small window -> exact rank scan
            float flo = k2f(s_lo), fhi = k2f(s_hi);
            int rr2 = rr - s_clo;
            for (int i = 0; i < nslots; i++) {
                float v = s_buf[i * THREADS + tid];
                if (v >= flo && v <= fhi) {
                    int pos = atomicAdd(&s_m2, 1);
                    if (pos < FBUF) s_fb[pos] = v;
                }
            }
            __syncthreads();
            int mm = min(s_m2, FBUF);
            if (tid < mm) {
                float v = s_fb[tid];
                int less = 0, leq = 0;
                for (int j2 = 0; j2 < mm; j2++) {
                    float u = s_fb[j2];
                    less += (u < v); leq += (u <= v);
                }
                if (less <= rr2 && rr2 < leq) s_T = v;   // ties write same value
            }
            __syncthreads();
        }
        thresh = s_T;
    } else {
        // ---- fallback: exact counting bisection over register data ----
        // invariant: cnt(< k2f(lo)) = clo <= k < cnt(<= k2f(hi)) = cle
        if (tid == 0) {
            unsigned lo, hi; int clo, cle;
            if (k < Clo)       { lo = 0x00800000u;  clo = 0;   hi = f2k(A) - 1u; cle = Clo;  }
            else if (k >= Che) { lo = f2k(B) + 1u;  clo = Che; hi = 0xFF7FFFFFu; cle = COLS; }
            else               { lo = f2k(A);       clo = Clo; hi = f2k(B);      cle = Che;  }
            s_lo = lo; s_hi = hi; s_clo = clo; s_cle = cle;
            if (lo >= hi) { s_done = 1; s_T = k2f(lo); }
        }
        __syncthreads();

        for (int iter = 0; iter < 96; iter++) {
            if (s_done) break;
            unsigned lo = s_lo, hi = s_hi;
            int clo = s_clo, cle = s_cle, cw = cle - clo;
            if (cw <= 64) break;
            unsigned p;
            if (iter & 1) {
                p = lo + ((hi - lo + 1u) >> 1);
            } else {
                float flo = k2f(lo), fhi = k2f(hi);
                float frac = ((float)(k - clo) + 0.5f) / (float)cw;
                p = f2k(flo + (fhi - flo) * frac);
                if (p <= lo) p = lo + 1u;
                if (p > hi)  p = hi;
            }
            float pf = k2f(p);
            int cnt = 0;
#pragma unroll
            for (int j = 0; j < PER; j++) cnt += (x[j] < pf);
#pragma unroll
            for (int o = 16; o; o >>= 1) cnt += __shfl_down_sync(0xffffffffu, cnt, o);
            if (lane == 0) s_part[wid] = cnt;
            __syncthreads();
            if (tid == 0) {
                int ct = 0;
#pragma unroll
                for (int w = 0; w < 8; w++) ct += s_part[w];
                if (ct > k) { s_hi = p - 1u; s_cle = ct; }
                else        { s_lo = p;      s_clo = ct; }
                if (s_lo >= s_hi) { s_done = 1; s_T = k2f(s_lo); }
            }
            __syncthreads();
        }

        if (!s_done) {
            float flo = k2f(s_lo), fhi = k2f(s_hi);
            int rr2 = k - s_clo;
#pragma unroll
            for (int j = 0; j < PER; j++) {
                float v = x[j];
                if (v >= flo && v <= fhi) {
                    int pos = atomicAdd(&s_m2, 1);
                    if (pos < FBUF) s_fb[pos] = v;
                }
            }
            __syncthreads();
            int mm = min(s_m2, FBUF);
            if (tid < mm) {
                float v = s_fb[tid];
                int less = 0, leq = 0;
                for (int j2 = 0; j2 < mm; j2++) {
                    float u = s_fb[j2];
                    less += (u < v); leq += (u <= v);
                }
                if (less <= rr2 && rr2 < leq) s_T = v;
            }
            __syncthreads();
        }
        thresh = s_T;
    }

    // ---- epilogue: we = relu(x - thresh) * exp(x), normalize, store ----
    float acc = 0.0f;
#pragma unroll
    for (int j = 0; j < PER; j++) {
        float w  = fmaxf(x[j] - thresh, 0.0f);
        float we = w * __expf(x[j]);
        x[j] = we;
        acc += we;
    }
#pragma unroll
    for (int o = 16; o; o >>= 1) acc += __shfl_down_sync(0xffffffffu, acc, o);
    if (lane == 0) s_facc[wid] = acc;
    __syncthreads();
    if (tid == 0) {
        float s = 0.0f;
#pragma unroll
        for (int w = 0; w < 8; w++) s += s_facc[w];
        s_inv = 1.0f / s;
    }
    __syncthreads();
    const float inv = s_inv;

#pragma unroll
    for (int j = 0; j < PER / 4; j++) {
        float4 v;
        v.x = x[4*j+0] * inv;
        v.y = x[4*j+1] * inv;
        v.z = x[4*j+2] * inv;
        v.w = x[4*j+3] * inv;
        ((float4*)op)[j * THREADS + tid] = v;
    }
}

extern "C" void kernel_launch(void* const* d_in, const int* in_sizes, int n_in,
                              void* d_out, int out_size) {
    const float* in     = (const float*)d_in[0];
    const float* rate_p = (const float*)d_in[1];
    float*       out    = (float*)d_out;
    const int rows = in_sizes[0] / COLS;   // 8192
    rsoftmax_kernel<<<rows, THREADS>>>(in, rate_p, out);
}